// round 16
// baseline (speedup 1.0000x reference)
#include <cuda_runtime.h>
#include <cuda_fp16.h>
#include <math.h>
#include <stdint.h>

#define B_ROWS 1024
#define M_TOT  200000
#define D_INP  256
#define DIM    128
#define D_OUT  10
#define M_PAD  200192            /* 1564*128 = 3128*64 */
#define N_MT   1564              /* k_main m-tiles of 128 */
#define N_T2   3144              /* k_proj tiles of 64: 16 query + 3128 cand */
#define NBLK   782               /* histogram blocks of 256 */
#define MAX_SL 160               /* max tile slices */

// ---------------------------------------------------------------- helpers
__device__ __forceinline__ uint32_t smem_to_u32(const void* p) {
    uint32_t a;
    asm("{ .reg .u64 t; cvta.to.shared.u64 t, %1; cvt.u32.u64 %0, t; }"
        : "=r"(a) : "l"(p));
    return a;
}
__device__ __forceinline__ void ldsm4(uint32_t r[4], uint32_t addr) {
    asm volatile("ldmatrix.sync.aligned.m8n8.x4.shared.b16 {%0,%1,%2,%3}, [%4];"
                 : "=r"(r[0]), "=r"(r[1]), "=r"(r[2]), "=r"(r[3]) : "r"(addr));
}
__device__ __forceinline__ void mma16816(float c[4], const uint32_t a[4],
                                         const uint32_t b0, const uint32_t b1) {
    asm volatile("mma.sync.aligned.m16n8k16.row.col.f32.f16.f16.f32 "
                 "{%0,%1,%2,%3}, {%4,%5,%6,%7}, {%8,%9}, {%0,%1,%2,%3};"
                 : "+f"(c[0]), "+f"(c[1]), "+f"(c[2]), "+f"(c[3])
                 : "r"(a[0]), "r"(a[1]), "r"(a[2]), "r"(a[3]), "r"(b0), "r"(b1));
}
__device__ __forceinline__ void mma16816h(uint32_t c[2], const uint32_t a[4],
                                          const uint32_t b0, const uint32_t b1) {
    asm volatile("mma.sync.aligned.m16n8k16.row.col.f16.f16.f16.f16 "
                 "{%0,%1}, {%2,%3,%4,%5}, {%6,%7}, {%0,%1};"
                 : "+r"(c[0]), "+r"(c[1])
                 : "r"(a[0]), "r"(a[1]), "r"(a[2]), "r"(a[3]), "r"(b0), "r"(b1));
}
__device__ __forceinline__ float sqrt_approx(float x) {
    float r; asm("sqrt.approx.f32 %0, %1;" : "=f"(r) : "f"(x)); return r;
}
__device__ __forceinline__ void lda_frag(uint32_t a[4], uint32_t base, int R0,
                                         int ks, int lane, int rstride) {
    int row = R0 + (lane & 15);
    int kb  = ks * 32 + ((lane >> 4) << 4);
    ldsm4(a, base + row * rstride + (kb ^ ((row & 7) << 4)));
}
__device__ __forceinline__ void ldb_frag(uint32_t b[4], uint32_t base, int N0,
                                         int ks, int lane, int rstride) {
    int row = N0 + (lane & 7) + ((lane >> 4) << 3);
    int kb  = ks * 32 + ((lane >> 3) & 1) * 16;
    ldsm4(b, base + row * rstride + (kb ^ ((row & 7) << 4)));
}

// ---------------------------------------------------------------- scratch
__device__ __half g_h   [B_ROWS * DIM];
__device__ float  g_hn2 [B_ROWS];
__device__ __half g_hc  [(size_t)M_PAD * DIM];
__device__ float  g_hcn2[M_PAD];
__device__ int    g_src [M_PAD];
__device__ int    g_cls [M_PAD];
__device__ int    g_bh  [NBLK * D_OUT];
__device__ int    g_boff[NBLK * D_OUT];
__device__ int    g_coff[D_OUT];
__device__ float  g_part2[(size_t)2 * MAX_SL * 512 * D_OUT];

// ---------------------------------------------------------------- sort
__global__ void k_hist(const int* __restrict__ cy) {
    __shared__ int cnt[D_OUT];
    int t = threadIdx.x, b = blockIdx.x;
    if (t < D_OUT) cnt[t] = 0;
    __syncthreads();
    int m = b * 256 + t;
    if (m < M_TOT) atomicAdd(&cnt[cy[m]], 1);
    __syncthreads();
    if (t < D_OUT) g_bh[b * D_OUT + t] = cnt[t];
}
__global__ void k_scan() {
    __shared__ int tot[D_OUT];
    int w = threadIdx.x >> 5, lane = threadIdx.x & 31;
    if (w < D_OUT) {
        int run = 0;
        for (int base = 0; base < NBLK; base += 32) {
            int b = base + lane;
            int v = (b < NBLK) ? g_bh[b * D_OUT + w] : 0;
            int s = v;
#pragma unroll
            for (int o = 1; o < 32; o <<= 1) {
                int t = __shfl_up_sync(0xFFFFFFFF, s, o);
                if (lane >= o) s += t;
            }
            if (b < NBLK) g_boff[b * D_OUT + w] = run + s - v;
            run += __shfl_sync(0xFFFFFFFF, s, 31);
        }
        if (lane == 0) tot[w] = run;
    }
    __syncthreads();
    if (threadIdx.x == 0) {
        int off = 0;
        for (int c = 0; c < D_OUT; c++) { g_coff[c] = off; off += tot[c]; }
    }
    for (int p = M_TOT + threadIdx.x; p < M_PAD; p += 320) g_cls[p] = D_OUT - 1;
}
__global__ void k_rank(const int* __restrict__ cy) {
    __shared__ int cls[256];
    int t = threadIdx.x, b = blockIdx.x;
    int m = b * 256 + t;
    int c = (m < M_TOT) ? cy[m] : -1;
    cls[t] = c;
    __syncthreads();
    if (m < M_TOT) {
        int r = 0;
        for (int j = 0; j < t; j++) r += (cls[j] == c);
        int pos = g_coff[c] + g_boff[b * D_OUT + c] + r;
        g_src[pos] = m;
        g_cls[pos] = c;
    }
}

// ---------------------------------------------------------------- k_proj (R15 frozen)
#define PW2    0
#define PA2    65536
#define PBIAS2 98304
#define PSRC2  98816
#define PPART2 99072
#define SMEM_P2_BYTES 99584

__global__ __launch_bounds__(256, 2) void k_proj(const float* __restrict__ x,
                                                 const float* __restrict__ cx,
                                                 const float* __restrict__ W,
                                                 const float* __restrict__ be) {
    extern __shared__ char smem[];
    uint32_t sb = smem_to_u32(smem);
    float* bias_s = (float*)(smem + PBIAS2);
    int*   srcs   = (int*)(smem + PSRC2);
    float* part   = (float*)(smem + PPART2);
    int tid = threadIdx.x, lane = tid & 31, wid = tid >> 5;
    int wr = wid & 3, wc = wid >> 2;

#pragma unroll
    for (int i = 0; i < 16; i++) {
        int idx = tid + i * 256;
        int r = idx >> 5, kb = (idx & 31) * 16;
        const float4* s4 = (const float4*)(W + (size_t)r * D_INP + kb / 2);
        float4 v0 = s4[0], v1 = s4[1];
        __half2 h0 = __floats2half2_rn(v0.x, v0.y), h1 = __floats2half2_rn(v0.z, v0.w);
        __half2 h2 = __floats2half2_rn(v1.x, v1.y), h3 = __floats2half2_rn(v1.z, v1.w);
        *(uint4*)(smem + PW2 + r * 512 + (kb ^ ((r & 7) << 4))) =
            make_uint4(*(uint32_t*)&h0, *(uint32_t*)&h1, *(uint32_t*)&h2, *(uint32_t*)&h3);
    }
    if (tid < 128) bias_s[tid] = be[tid];

    for (int t = blockIdx.x; t < N_T2; t += gridDim.x) {
        bool isq = t < 16;
        int tile = isq ? t : t - 16;
        __syncthreads();
        if (tid < 64) {
            int p = tile * 64 + tid;
            srcs[tid] = isq ? p : ((p < M_TOT) ? g_src[p] : 0);
        }
        __syncthreads();
        const float* mat = isq ? x : cx;
#pragma unroll
        for (int i = 0; i < 8; i++) {
            int idx = tid + i * 256;
            int r = idx >> 5, kb = (idx & 31) * 16;
            const float4* s4 = (const float4*)(mat + (size_t)srcs[r] * D_INP + kb / 2);
            float4 v0 = s4[0], v1 = s4[1];
            __half2 h0 = __floats2half2_rn(v0.x, v0.y), h1 = __floats2half2_rn(v0.z, v0.w);
            __half2 h2 = __floats2half2_rn(v1.x, v1.y), h3 = __floats2half2_rn(v1.z, v1.w);
            *(uint4*)(smem + PA2 + r * 512 + (kb ^ ((r & 7) << 4))) =
                make_uint4(*(uint32_t*)&h0, *(uint32_t*)&h1, *(uint32_t*)&h2, *(uint32_t*)&h3);
        }
        __syncthreads();

        float acc[8][4];
#pragma unroll
        for (int n = 0; n < 8; n++)
#pragma unroll
            for (int j = 0; j < 4; j++) acc[n][j] = 0.f;
#pragma unroll
        for (int ks = 0; ks < 16; ks++) {
            uint32_t a[4], bf[4][4];
            lda_frag(a, sb + PA2, wr * 16, ks, lane, 512);
#pragma unroll
            for (int p = 0; p < 4; p++)
                ldb_frag(bf[p], sb + PW2, wc * 64 + p * 16, ks, lane, 512);
#pragma unroll
            for (int nt = 0; nt < 8; nt++)
                mma16816(acc[nt], a, bf[nt >> 1][(nt & 1) * 2], bf[nt >> 1][(nt & 1) * 2 + 1]);
        }

        __half* out_h  = isq ? g_h   : g_hc;
        float*  out_n2 = isq ? g_hn2 : g_hcn2;
        float sumsq[2] = {0.f, 0.f};
#pragma unroll
        for (int hr = 0; hr < 2; hr++) {
            int row = wr * 16 + (lane >> 2) + hr * 8;
            size_t gm = (size_t)tile * 64 + row;
#pragma unroll
            for (int nt = 0; nt < 8; nt++) {
                int d0 = wc * 64 + nt * 8 + (lane & 3) * 2;
                float v0 = acc[nt][hr * 2 + 0] + bias_s[d0];
                float v1 = acc[nt][hr * 2 + 1] + bias_s[d0 + 1];
                __half2 hp = __floats2half2_rn(v0, v1);
                float2 vr = __half22float2(hp);
                sumsq[hr] = fmaf(vr.x, vr.x, sumsq[hr]);
                sumsq[hr] = fmaf(vr.y, vr.y, sumsq[hr]);
                *(__half2*)(out_h + gm * DIM + d0) = hp;
            }
        }
#pragma unroll
        for (int hr = 0; hr < 2; hr++) {
            float v = sumsq[hr];
            v += __shfl_xor_sync(0xFFFFFFFF, v, 1);
            v += __shfl_xor_sync(0xFFFFFFFF, v, 2);
            if ((lane & 3) == 0) {
                int row = wr * 16 + (lane >> 2) + hr * 8;
                part[row * 2 + wc] = v;
            }
        }
        __syncthreads();
        if (tid < 64) {
            size_t gm = (size_t)tile * 64 + tid;
            float v = part[tid * 2] + part[tid * 2 + 1];
            out_n2[gm] = (isq || gm < M_TOT) ? v : 3e38f;
        }
    }
}

// ---------------------------------------------------------------- k_main v4
// 512 threads / 16 warps, 1 CTA/SM. CTA = (query half qh of 512 rows, slice).
// A (512 query rows) resident in smem for entire kernel; B tiles stream.
// Warp = 32 query rows (strips wid*32, wid*32+16) x 128 candidates, fp16 accum.
#define KM_A   0        /* 512 rows x 256B = 128KB */
#define KM_B   131072   /* 128 rows x 256B = 32KB  */
#define KM_CN  163840   /* 512B */
#define KM_CLS 164352   /* 512B */
#define KM_SS  164864   /* 512 x 10 f32 = 20KB */
#define SMEM_M4 (KM_SS + 512 * D_OUT * 4)

__device__ __forceinline__ void epi_slice_h(const uint32_t acc[2], float hn0, float hn1,
                                            float c0, float c1, float (&rs)[2]) {
    float2 f01 = __half22float2(*(const __half2*)&acc[0]);
    float2 f23 = __half22float2(*(const __half2*)&acc[1]);
    float sq0 = fmaxf(fmaf(-2.f, f01.x, hn0 + c0), 1e-30f);
    float sq1 = fmaxf(fmaf(-2.f, f01.y, hn0 + c1), 1e-30f);
    float sq2 = fmaxf(fmaf(-2.f, f23.x, hn1 + c0), 1e-30f);
    float sq3 = fmaxf(fmaf(-2.f, f23.y, hn1 + c1), 1e-30f);
    rs[0] += __expf(-sqrt_approx(sq0)) + __expf(-sqrt_approx(sq1));
    rs[1] += __expf(-sqrt_approx(sq2)) + __expf(-sqrt_approx(sq3));
}

__device__ __forceinline__ void red_store4(float (&rs)[2], float* s_s,
                                           int rowbase, int cls, int lane) {
#pragma unroll
    for (int hr = 0; hr < 2; hr++) {
        float v = rs[hr];
        v += __shfl_xor_sync(0xFFFFFFFF, v, 1);
        v += __shfl_xor_sync(0xFFFFFFFF, v, 2);
        if ((lane & 3) == 0)
            s_s[(rowbase + (lane >> 2) + hr * 8) * D_OUT + cls] += v;
    }
}

__global__ __launch_bounds__(512, 1) void k_main() {
    extern __shared__ char smem[];
    uint32_t sb = smem_to_u32(smem);
    float* s_s   = (float*)(smem + KM_SS);
    float* cn_s  = (float*)(smem + KM_CN);
    int*   cls_s = (int*)(smem + KM_CLS);
    int tid = threadIdx.x, lane = tid & 31, wid = tid >> 5;   // 16 warps
    uint32_t AA = sb + KM_A, BB = sb + KM_B;
    int qh    = blockIdx.x & 1;
    int slice = blockIdx.x >> 1;
    int nsl   = gridDim.x >> 1;
    int t0 = (int)(((long long)slice * N_MT) / nsl);
    int t1 = (int)(((long long)(slice + 1) * N_MT) / nsl);

    for (int i = tid; i < 512 * D_OUT; i += 512) s_s[i] = 0.f;

    // A: this half's 512 query rows, loaded ONCE (8192 x 16B / 512 thr)
#pragma unroll
    for (int i = 0; i < 16; i++) {
        int idx = tid + i * 512;
        int r = idx >> 4, kb = (idx & 15) * 16;
        *(uint4*)(smem + KM_A + r * 256 + (kb ^ ((r & 7) << 4))) =
            *(const uint4*)((const char*)g_h + ((size_t)qh * 512 + r) * 256 + kb);
    }
    int rbq = qh * 512 + wid * 32 + (lane >> 2);
    float hn0 = g_hn2[rbq],      hn1 = g_hn2[rbq + 8];
    float hn2 = g_hn2[rbq + 16], hn3 = g_hn2[rbq + 24];
    __syncthreads();

    uint32_t acc[2][16][2];    // [strip][ntile][reg]

    for (int mt = t0; mt < t1; mt++) {
        __syncthreads();       // prev tile MMA done reading B
        int mbase = mt * 128;
#pragma unroll
        for (int i = 0; i < 4; i++) {
            int idx = tid + i * 512;
            int r = idx >> 4, kb = (idx & 15) * 16;
            *(uint4*)(smem + KM_B + r * 256 + (kb ^ ((r & 7) << 4))) =
                *(const uint4*)((const char*)g_hc + ((size_t)mbase + r) * 256 + kb);
        }
        if (tid < 128) {
            cn_s[tid]  = g_hcn2[mbase + tid];
            cls_s[tid] = g_cls[mbase + tid];
        }
        __syncthreads();
        int c_lo = cls_s[0], c_hi = cls_s[127];
        const float* cnp = cn_s + (lane & 3) * 2;

        // ---- MMA: 32 rows x 128 cols per warp ----
#pragma unroll
        for (int s = 0; s < 2; s++)
#pragma unroll
            for (int n = 0; n < 16; n++) { acc[s][n][0] = 0u; acc[s][n][1] = 0u; }
#pragma unroll
        for (int ks = 0; ks < 8; ks++) {
            uint32_t alo[4], ahi[4];
            lda_frag(alo, AA, wid * 32,      ks, lane, 256);
            lda_frag(ahi, AA, wid * 32 + 16, ks, lane, 256);
#pragma unroll
            for (int half = 0; half < 2; half++) {
                uint32_t bf[4][4];
#pragma unroll
                for (int p = 0; p < 4; p++)
                    ldb_frag(bf[p], BB, half * 64 + p * 16, ks, lane, 256);
#pragma unroll
                for (int nt = 0; nt < 8; nt++) {
                    mma16816h(acc[0][half * 8 + nt], alo,
                              bf[nt >> 1][(nt & 1) * 2], bf[nt >> 1][(nt & 1) * 2 + 1]);
                    mma16816h(acc[1][half * 8 + nt], ahi,
                              bf[nt >> 1][(nt & 1) * 2], bf[nt >> 1][(nt & 1) * 2 + 1]);
                }
            }
        }

        // ---- epilogue ----
        if (c_lo == c_hi) {
            float rs0[2] = {0.f, 0.f}, rs1[2] = {0.f, 0.f};
#pragma unroll
            for (int nt = 0; nt < 16; nt++) {
                float c0 = cnp[nt * 8], c1 = cnp[nt * 8 + 1];
                epi_slice_h(acc[0][nt], hn0, hn1, c0, c1, rs0);
                epi_slice_h(acc[1][nt], hn2, hn3, c0, c1, rs1);
            }
            red_store4(rs0, s_s, wid * 32,      c_lo, lane);
            red_store4(rs1, s_s, wid * 32 + 16, c_lo, lane);
        } else {
            const int* clp = cls_s + (lane & 3) * 2;
#pragma unroll 1
            for (int s = 0; s < 2; s++) {
                float h0 = s ? hn2 : hn0, h1 = s ? hn3 : hn1;
                float rsa[D_OUT], rsb[D_OUT];
#pragma unroll
                for (int c = 0; c < D_OUT; c++) { rsa[c] = 0.f; rsb[c] = 0.f; }
#pragma unroll
                for (int nt = 0; nt < 16; nt++) {
                    float c0 = cnp[nt * 8], c1 = cnp[nt * 8 + 1];
                    int cl0 = clp[nt * 8], cl1 = clp[nt * 8 + 1];
                    float2 f01 = __half22float2(*(const __half2*)&acc[s][nt][0]);
                    float2 f23 = __half22float2(*(const __half2*)&acc[s][nt][1]);
                    float e0 = __expf(-sqrt_approx(fmaxf(fmaf(-2.f, f01.x, h0 + c0), 1e-30f)));
                    float e1 = __expf(-sqrt_approx(fmaxf(fmaf(-2.f, f01.y, h0 + c1), 1e-30f)));
                    float e2 = __expf(-sqrt_approx(fmaxf(fmaf(-2.f, f23.x, h1 + c0), 1e-30f)));
                    float e3 = __expf(-sqrt_approx(fmaxf(fmaf(-2.f, f23.y, h1 + c1), 1e-30f)));
                    rsa[cl0] += e0; rsa[cl1] += e1;
                    rsb[cl0] += e2; rsb[cl1] += e3;
                }
                for (int cc = c_lo; cc <= c_hi; cc++) {
                    float rs[2] = {rsa[cc], rsb[cc]};
                    red_store4(rs, s_s, wid * 32 + s * 16, cc, lane);
                }
            }
        }
    }
    __syncthreads();
    float* dst = g_part2 + ((size_t)(qh * MAX_SL + slice)) * (512 * D_OUT);
    for (int i = tid; i < 512 * D_OUT; i += 512) dst[i] = s_s[i];
}

// ---------------------------------------------------------------- k_final
__global__ void k_final(float* __restrict__ out, int nsl) {
    __shared__ float red[320];
    int b = blockIdx.x, t = threadIdx.x;    // 320 threads
    int g = t / 10, c = t - g * 10;
    int qh = b >> 9, r = b & 511;
    float s = 0.f;
    for (int p = g; p < nsl; p += 32)
        s += g_part2[((size_t)(qh * MAX_SL + p) * 512 + r) * D_OUT + c];
    red[t] = s;
    __syncthreads();
    if (t < 160) red[t] += red[t + 160]; __syncthreads();
    if (t < 80)  red[t] += red[t + 80];  __syncthreads();
    if (t < 40)  red[t] += red[t + 40];  __syncthreads();
    if (t < 20)  red[t] += red[t + 20];  __syncthreads();
    if (t < 10)  red[t] += red[t + 10];
    __syncthreads();
    if (t < 10) {
        float tot = 0.f;
#pragma unroll
        for (int cc = 0; cc < 10; cc++) tot += red[cc];
        out[b * D_OUT + t] = logf(red[t] / tot + 1e-7f);
    }
}

// ---------------------------------------------------------------- launch
extern "C" void kernel_launch(void* const* d_in, const int* in_sizes, int n_in,
                              void* d_out, int out_size) {
    const float* x  = (const float*)d_in[0];
    const float* cx = (const float*)d_in[2];
    const int*   cy = (const int*)d_in[3];
    const float* W  = (const float*)d_in[4];
    const float* be = (const float*)d_in[5];
    float* out = (float*)d_out;

    int dev = 0;
    cudaGetDevice(&dev);
    int nsm = 148;
    cudaDeviceGetAttribute(&nsm, cudaDevAttrMultiProcessorCount, dev);
    if (nsm < 2) nsm = 148;
    int nsl = nsm / 2;                  // 2 halves x nsl slices = <=nsm CTAs
    if (nsl > MAX_SL) nsl = MAX_SL;
    int grid_main = 2 * nsl;

    cudaFuncSetAttribute(k_proj, cudaFuncAttributeMaxDynamicSharedMemorySize, SMEM_P2_BYTES);
    cudaFuncSetAttribute(k_main, cudaFuncAttributeMaxDynamicSharedMemorySize, SMEM_M4);

    k_hist<<<NBLK, 256>>>(cy);
    k_scan<<<1, 320>>>();
    k_rank<<<NBLK, 256>>>(cy);
    k_proj<<<2 * nsm, 256, SMEM_P2_BYTES>>>(x, cx, W, be);
    k_main<<<grid_main, 512, SMEM_M4>>>();
    k_final<<<B_ROWS, 320>>>(out, nsl);
}

// round 17
// speedup vs baseline: 1.9052x; 1.9052x over previous
#include <cuda_runtime.h>
#include <cuda_fp16.h>
#include <math.h>
#include <stdint.h>

#define B_ROWS 1024
#define M_TOT  200000
#define D_INP  256
#define DIM    128
#define D_OUT  10
#define M_PAD  200192            /* 1564*128 = 3128*64 */
#define N_MT   1564              /* k_main m-tiles of 128 */
#define N_T2   3144              /* k_proj tiles of 64: 16 query + 3128 cand */
#define NBLK   782               /* histogram blocks of 256 */
#define MAX_CTAS 512

// ---------------------------------------------------------------- helpers
__device__ __forceinline__ uint32_t smem_to_u32(const void* p) {
    uint32_t a;
    asm("{ .reg .u64 t; cvta.to.shared.u64 t, %1; cvt.u32.u64 %0, t; }"
        : "=r"(a) : "l"(p));
    return a;
}
__device__ __forceinline__ void ldsm4(uint32_t r[4], uint32_t addr) {
    asm volatile("ldmatrix.sync.aligned.m8n8.x4.shared.b16 {%0,%1,%2,%3}, [%4];"
                 : "=r"(r[0]), "=r"(r[1]), "=r"(r[2]), "=r"(r[3]) : "r"(addr));
}
__device__ __forceinline__ void mma16816(float c[4], const uint32_t a[4],
                                         const uint32_t b0, const uint32_t b1) {
    asm volatile("mma.sync.aligned.m16n8k16.row.col.f32.f16.f16.f32 "
                 "{%0,%1,%2,%3}, {%4,%5,%6,%7}, {%8,%9}, {%0,%1,%2,%3};"
                 : "+f"(c[0]), "+f"(c[1]), "+f"(c[2]), "+f"(c[3])
                 : "r"(a[0]), "r"(a[1]), "r"(a[2]), "r"(a[3]), "r"(b0), "r"(b1));
}
__device__ __forceinline__ float sqrt_approx(float x) {
    float r; asm("sqrt.approx.f32 %0, %1;" : "=f"(r) : "f"(x)); return r;
}
__device__ __forceinline__ void lda_frag(uint32_t a[4], uint32_t base, int R0,
                                         int ks, int lane, int rstride) {
    int row = R0 + (lane & 15);
    int kb  = ks * 32 + ((lane >> 4) << 4);
    ldsm4(a, base + row * rstride + (kb ^ ((row & 7) << 4)));
}
__device__ __forceinline__ void ldb_frag(uint32_t b[4], uint32_t base, int N0,
                                         int ks, int lane, int rstride) {
    int row = N0 + (lane & 7) + ((lane >> 4) << 3);
    int kb  = ks * 32 + ((lane >> 3) & 1) * 16;
    ldsm4(b, base + row * rstride + (kb ^ ((row & 7) << 4)));
}

// ---------------------------------------------------------------- scratch
__device__ __half g_h   [B_ROWS * DIM];
__device__ float  g_hn2 [B_ROWS];
__device__ __half g_hc  [(size_t)M_PAD * DIM];
__device__ float  g_hcn2[M_PAD];
__device__ int    g_src [M_PAD];
__device__ int    g_cls [M_PAD];
__device__ int    g_bh  [NBLK * D_OUT];
__device__ int    g_boff[NBLK * D_OUT];
__device__ int    g_coff[D_OUT];
__device__ float  g_part[(size_t)MAX_CTAS * B_ROWS * D_OUT];

// ---------------------------------------------------------------- sort
__global__ void k_hist(const int* __restrict__ cy) {
    __shared__ int cnt[D_OUT];
    int t = threadIdx.x, b = blockIdx.x;
    if (t < D_OUT) cnt[t] = 0;
    __syncthreads();
    int m = b * 256 + t;
    if (m < M_TOT) atomicAdd(&cnt[cy[m]], 1);
    __syncthreads();
    if (t < D_OUT) g_bh[b * D_OUT + t] = cnt[t];
}
__global__ void k_scan() {
    __shared__ int tot[D_OUT];
    int w = threadIdx.x >> 5, lane = threadIdx.x & 31;
    if (w < D_OUT) {
        int run = 0;
        for (int base = 0; base < NBLK; base += 32) {
            int b = base + lane;
            int v = (b < NBLK) ? g_bh[b * D_OUT + w] : 0;
            int s = v;
#pragma unroll
            for (int o = 1; o < 32; o <<= 1) {
                int t = __shfl_up_sync(0xFFFFFFFF, s, o);
                if (lane >= o) s += t;
            }
            if (b < NBLK) g_boff[b * D_OUT + w] = run + s - v;
            run += __shfl_sync(0xFFFFFFFF, s, 31);
        }
        if (lane == 0) tot[w] = run;
    }
    __syncthreads();
    if (threadIdx.x == 0) {
        int off = 0;
        for (int c = 0; c < D_OUT; c++) { g_coff[c] = off; off += tot[c]; }
    }
    for (int p = M_TOT + threadIdx.x; p < M_PAD; p += 320) g_cls[p] = D_OUT - 1;
}
__global__ void k_rank(const int* __restrict__ cy) {
    __shared__ int cls[256];
    int t = threadIdx.x, b = blockIdx.x;
    int m = b * 256 + t;
    int c = (m < M_TOT) ? cy[m] : -1;
    cls[t] = c;
    __syncthreads();
    if (m < M_TOT) {
        int r = 0;
        for (int j = 0; j < t; j++) r += (cls[j] == c);
        int pos = g_coff[c] + g_boff[b * D_OUT + c] + r;
        g_src[pos] = m;
        g_cls[pos] = c;
    }
}

// ---------------------------------------------------------------- k_proj v2.1
// Persistent W in smem, 64-row tiles, 256 threads, 2 CTAs/SM.
// srcs read directly (warp-uniform L1 loads) — no smem staging, 2 fewer syncs.
#define PW2    0          /* 128 x 512B = 64KB fp16 W swizzled */
#define PA2    65536      /* 64 x 512B  = 32KB */
#define PBIAS2 98304      /* 512B */
#define PPART2 98816      /* 512B */
#define SMEM_P2_BYTES 99328

__global__ __launch_bounds__(256, 2) void k_proj(const float* __restrict__ x,
                                                 const float* __restrict__ cx,
                                                 const float* __restrict__ W,
                                                 const float* __restrict__ be) {
    extern __shared__ char smem[];
    uint32_t sb = smem_to_u32(smem);
    float* bias_s = (float*)(smem + PBIAS2);
    float* part   = (float*)(smem + PPART2);
    int tid = threadIdx.x, lane = tid & 31, wid = tid >> 5;
    int wr = wid & 3, wc = wid >> 2;

    // W -> smem fp16 once (4096 x 16B over 256 threads)
#pragma unroll
    for (int i = 0; i < 16; i++) {
        int idx = tid + i * 256;
        int r = idx >> 5, kb = (idx & 31) * 16;
        const float4* s4 = (const float4*)(W + (size_t)r * D_INP + kb / 2);
        float4 v0 = s4[0], v1 = s4[1];
        __half2 h0 = __floats2half2_rn(v0.x, v0.y), h1 = __floats2half2_rn(v0.z, v0.w);
        __half2 h2 = __floats2half2_rn(v1.x, v1.y), h3 = __floats2half2_rn(v1.z, v1.w);
        *(uint4*)(smem + PW2 + r * 512 + (kb ^ ((r & 7) << 4))) =
            make_uint4(*(uint32_t*)&h0, *(uint32_t*)&h1, *(uint32_t*)&h2, *(uint32_t*)&h3);
    }
    if (tid < 128) bias_s[tid] = be[tid];

    for (int t = blockIdx.x; t < N_T2; t += gridDim.x) {
        bool isq = t < 16;
        int tile = isq ? t : t - 16;
        __syncthreads();   // prior tile MMA readers done with PA2
        // gather 64 rows fp32->fp16 (2048 x 16B over 256 threads)
        // row index r is warp-uniform -> g_src load is a uniform L1 hit
        const float* mat = isq ? x : cx;
#pragma unroll
        for (int i = 0; i < 8; i++) {
            int idx = tid + i * 256;
            int r = idx >> 5, kb = (idx & 31) * 16;
            int p = tile * 64 + r;
            int srow = isq ? p : ((p < M_TOT) ? g_src[p] : 0);
            const float4* s4 = (const float4*)(mat + (size_t)srow * D_INP + kb / 2);
            float4 v0 = s4[0], v1 = s4[1];
            __half2 h0 = __floats2half2_rn(v0.x, v0.y), h1 = __floats2half2_rn(v0.z, v0.w);
            __half2 h2 = __floats2half2_rn(v1.x, v1.y), h3 = __floats2half2_rn(v1.z, v1.w);
            *(uint4*)(smem + PA2 + r * 512 + (kb ^ ((r & 7) << 4))) =
                make_uint4(*(uint32_t*)&h0, *(uint32_t*)&h1, *(uint32_t*)&h2, *(uint32_t*)&h3);
        }
        __syncthreads();

        float acc[8][4];
#pragma unroll
        for (int n = 0; n < 8; n++)
#pragma unroll
            for (int j = 0; j < 4; j++) acc[n][j] = 0.f;
#pragma unroll
        for (int ks = 0; ks < 16; ks++) {
            uint32_t a[4], bf[4][4];
            lda_frag(a, sb + PA2, wr * 16, ks, lane, 512);
#pragma unroll
            for (int p = 0; p < 4; p++)
                ldb_frag(bf[p], sb + PW2, wc * 64 + p * 16, ks, lane, 512);
#pragma unroll
            for (int nt = 0; nt < 8; nt++)
                mma16816(acc[nt], a, bf[nt >> 1][(nt & 1) * 2], bf[nt >> 1][(nt & 1) * 2 + 1]);
        }

        __half* out_h  = isq ? g_h   : g_hc;
        float*  out_n2 = isq ? g_hn2 : g_hcn2;
        float sumsq[2] = {0.f, 0.f};
#pragma unroll
        for (int hr = 0; hr < 2; hr++) {
            int row = wr * 16 + (lane >> 2) + hr * 8;
            size_t gm = (size_t)tile * 64 + row;
#pragma unroll
            for (int nt = 0; nt < 8; nt++) {
                int d0 = wc * 64 + nt * 8 + (lane & 3) * 2;
                float v0 = acc[nt][hr * 2 + 0] + bias_s[d0];
                float v1 = acc[nt][hr * 2 + 1] + bias_s[d0 + 1];
                __half2 hp = __floats2half2_rn(v0, v1);
                float2 vr = __half22float2(hp);
                sumsq[hr] = fmaf(vr.x, vr.x, sumsq[hr]);
                sumsq[hr] = fmaf(vr.y, vr.y, sumsq[hr]);
                *(__half2*)(out_h + gm * DIM + d0) = hp;
            }
        }
#pragma unroll
        for (int hr = 0; hr < 2; hr++) {
            float v = sumsq[hr];
            v += __shfl_xor_sync(0xFFFFFFFF, v, 1);
            v += __shfl_xor_sync(0xFFFFFFFF, v, 2);
            if ((lane & 3) == 0) {
                int row = wr * 16 + (lane >> 2) + hr * 8;
                part[row * 2 + wc] = v;
            }
        }
        __syncthreads();
        if (tid < 64) {
            size_t gm = (size_t)tile * 64 + tid;
            float v = part[tid * 2] + part[tid * 2 + 1];
            out_n2[gm] = (isq || gm < M_TOT) ? v : 3e38f;
        }
    }
}

// ---------------------------------------------------------------- k_main (round-10 proven, frozen)
#define KM_A   0        /* 256 rows x 256B = 64KB */
#define KM_B   65536    /* 128 rows x 256B = 32KB */
#define KM_CN  98304    /* 128 f32 */
#define KM_CLS 98816    /* 128 i32 */
#define KM_SS  99328    /* 2 x 1024 x 10 f32 = 80KB */
#define SMEM_MAIN_BYTES (KM_SS + 2 * B_ROWS * D_OUT * 4)

__device__ __forceinline__ void epi_reduce_store(float (&rs)[2], float* s_s,
                                                 int brow_base, int cls,
                                                 int wc, int lane) {
#pragma unroll
    for (int hr = 0; hr < 2; hr++) {
        float v = rs[hr];
        v += __shfl_xor_sync(0xFFFFFFFF, v, 1);
        v += __shfl_xor_sync(0xFFFFFFFF, v, 2);
        if ((lane & 3) == 0) {
            int brow = brow_base + (lane >> 2) + hr * 8;
            s_s[wc * (B_ROWS * D_OUT) + brow * D_OUT + cls] += v;
        }
    }
}

__device__ __forceinline__ void epi_slice(const float accP[4], float hn0, float hn1,
                                          float c0, float c1, float (&rs)[2]) {
    float sq0 = fmaxf(fmaf(-2.f, accP[0], hn0 + c0), 1e-30f);
    float sq1 = fmaxf(fmaf(-2.f, accP[1], hn0 + c1), 1e-30f);
    float sq2 = fmaxf(fmaf(-2.f, accP[2], hn1 + c0), 1e-30f);
    float sq3 = fmaxf(fmaf(-2.f, accP[3], hn1 + c1), 1e-30f);
    rs[0] += __expf(-sqrt_approx(sq0)) + __expf(-sqrt_approx(sq1));
    rs[1] += __expf(-sqrt_approx(sq2)) + __expf(-sqrt_approx(sq3));
}

// dual MMA: 256 A-rows (lo strip wr*16, hi strip 128+wr*16), shared ldb
__device__ __forceinline__ void mma2(float (&aL)[8][4], float (&aH)[8][4],
                                     uint32_t A, uint32_t B,
                                     int wr, int wc, int lane) {
#pragma unroll
    for (int n = 0; n < 8; n++)
#pragma unroll
        for (int j = 0; j < 4; j++) { aL[n][j] = 0.f; aH[n][j] = 0.f; }
#pragma unroll
    for (int ks = 0; ks < 8; ks++) {
        uint32_t alo[4], ahi[4], bf[4][4];
        lda_frag(alo, A, wr * 16,       ks, lane, 256);
        lda_frag(ahi, A, 128 + wr * 16, ks, lane, 256);
#pragma unroll
        for (int p = 0; p < 4; p++)
            ldb_frag(bf[p], B, wc * 64 + p * 16, ks, lane, 256);
#pragma unroll
        for (int nt = 0; nt < 8; nt++) {
            mma16816(aL[nt], alo, bf[nt >> 1][(nt & 1) * 2], bf[nt >> 1][(nt & 1) * 2 + 1]);
            mma16816(aH[nt], ahi, bf[nt >> 1][(nt & 1) * 2], bf[nt >> 1][(nt & 1) * 2 + 1]);
        }
    }
}

__device__ __forceinline__ void exp_inplace(float (&a)[8][4], float hn0, float hn1,
                                            const float* cnp) {
#pragma unroll
    for (int nt = 0; nt < 8; nt++) {
        float c0 = cnp[nt * 8], c1 = cnp[nt * 8 + 1];
        float sq0 = fmaxf(fmaf(-2.f, a[nt][0], hn0 + c0), 1e-30f);
        float sq1 = fmaxf(fmaf(-2.f, a[nt][1], hn0 + c1), 1e-30f);
        float sq2 = fmaxf(fmaf(-2.f, a[nt][2], hn1 + c0), 1e-30f);
        float sq3 = fmaxf(fmaf(-2.f, a[nt][3], hn1 + c1), 1e-30f);
        a[nt][0] = __expf(-sqrt_approx(sq0));
        a[nt][1] = __expf(-sqrt_approx(sq1));
        a[nt][2] = __expf(-sqrt_approx(sq2));
        a[nt][3] = __expf(-sqrt_approx(sq3));
    }
}

__global__ __launch_bounds__(512, 1) void k_main() {
    extern __shared__ char smem[];
    uint32_t sb = smem_to_u32(smem);
    float* s_s   = (float*)(smem + KM_SS);
    float* cn_s  = (float*)(smem + KM_CN);
    int*   cls_s = (int*)(smem + KM_CLS);
    int tid = threadIdx.x, lane = tid & 31, wid = tid >> 5;
    int wr = wid & 7, wc = wid >> 3;
    uint32_t AA = sb + KM_A, BB = sb + KM_B;

    for (int i = tid; i < 2 * B_ROWS * D_OUT; i += 512) s_s[i] = 0.f;

    float aL[8][4], aH[8][4];

    for (int mt = blockIdx.x; mt < N_MT; mt += gridDim.x) {
        __syncthreads();
        int mbase = mt * 128;
#pragma unroll
        for (int i = 0; i < 4; i++) {
            int idx = tid + i * 512;
            int r = idx >> 4, kb = (idx & 15) * 16;
            *(uint4*)(smem + KM_B + r * 256 + (kb ^ ((r & 7) << 4))) =
                *(const uint4*)((const char*)g_hc + ((size_t)mbase + r) * 256 + kb);
        }
        if (tid < 128) {
            cn_s[tid]  = g_hcn2[mbase + tid];
            cls_s[tid] = g_cls[mbase + tid];
        }
        int c_lo = g_cls[mbase], c_hi = g_cls[mbase + 127];
        const float* cnp = cn_s + wc * 64 + (lane & 3) * 2;

#pragma unroll 1
        for (int sc = 0; sc < 4; sc++) {
            if (sc) __syncthreads();
#pragma unroll
            for (int i = 0; i < 8; i++) {
                int idx = tid + i * 512;
                int r = idx >> 4, kb = (idx & 15) * 16;
                *(uint4*)(smem + KM_A + r * 256 + (kb ^ ((r & 7) << 4))) =
                    *(const uint4*)((const char*)g_h + ((size_t)sc * 256 + r) * 256 + kb);
            }
            __syncthreads();

            mma2(aL, aH, AA, BB, wr, wc, lane);

            int rbL = sc * 256 + wr * 16 + (lane >> 2);
            float hnL0 = g_hn2[rbL],       hnL1 = g_hn2[rbL + 8];
            float hnH0 = g_hn2[rbL + 128], hnH1 = g_hn2[rbL + 136];

            if (c_lo == c_hi) {
                float rsL[2] = {0.f, 0.f}, rsH[2] = {0.f, 0.f};
#pragma unroll
                for (int nt = 0; nt < 8; nt++) {
                    float c0 = cnp[nt * 8], c1 = cnp[nt * 8 + 1];
                    epi_slice(aL[nt], hnL0, hnL1, c0, c1, rsL);
                    epi_slice(aH[nt], hnH0, hnH1, c0, c1, rsH);
                }
                epi_reduce_store(rsL, s_s, sc * 256 + wr * 16,       c_lo, wc, lane);
                epi_reduce_store(rsH, s_s, sc * 256 + 128 + wr * 16, c_lo, wc, lane);
            } else {
                const int* clp = cls_s + wc * 64 + (lane & 3) * 2;
                exp_inplace(aL, hnL0, hnL1, cnp);
                exp_inplace(aH, hnH0, hnH1, cnp);
                for (int cc = c_lo; cc <= c_hi; cc++) {
                    float rsL[2] = {0.f, 0.f}, rsH[2] = {0.f, 0.f};
#pragma unroll
                    for (int nt = 0; nt < 8; nt++) {
                        int cl0 = clp[nt * 8], cl1 = clp[nt * 8 + 1];
                        rsL[0] += (cl0 == cc) ? aL[nt][0] : 0.f;
                        rsL[0] += (cl1 == cc) ? aL[nt][1] : 0.f;
                        rsL[1] += (cl0 == cc) ? aL[nt][2] : 0.f;
                        rsL[1] += (cl1 == cc) ? aL[nt][3] : 0.f;
                        rsH[0] += (cl0 == cc) ? aH[nt][0] : 0.f;
                        rsH[0] += (cl1 == cc) ? aH[nt][1] : 0.f;
                        rsH[1] += (cl0 == cc) ? aH[nt][2] : 0.f;
                        rsH[1] += (cl1 == cc) ? aH[nt][3] : 0.f;
                    }
                    epi_reduce_store(rsL, s_s, sc * 256 + wr * 16,       cc, wc, lane);
                    epi_reduce_store(rsH, s_s, sc * 256 + 128 + wr * 16, cc, wc, lane);
                }
            }
        }
    }
    __syncthreads();
    for (int i = tid; i < B_ROWS * D_OUT; i += 512)
        g_part[(size_t)blockIdx.x * (B_ROWS * D_OUT) + i] =
            s_s[i] + s_s[B_ROWS * D_OUT + i];
}

// ---------------------------------------------------------------- k_final
__global__ void k_final(float* __restrict__ out, int nctas) {
    __shared__ float red[320];
    int b = blockIdx.x, t = threadIdx.x;    // 320 threads
    int g = t / 10, c = t - g * 10;
    float s = 0.f;
    for (int p = g; p < nctas; p += 32)
        s += g_part[(size_t)p * (B_ROWS * D_OUT) + b * D_OUT + c];
    red[t] = s;
    __syncthreads();
    if (t < 160) red[t] += red[t + 160]; __syncthreads();
    if (t < 80)  red[t] += red[t + 80];  __syncthreads();
    if (t < 40)  red[t] += red[t + 40];  __syncthreads();
    if (t < 20)  red[t] += red[t + 20];  __syncthreads();
    if (t < 10)  red[t] += red[t + 10];
    __syncthreads();
    if (t < 10) {
        float tot = 0.f;
#pragma unroll
        for (int cc = 0; cc < 10; cc++) tot += red[cc];
        out[b * D_OUT + t] = logf(red[t] / tot + 1e-7f);
    }
}

// ---------------------------------------------------------------- launch
extern "C" void kernel_launch(void* const* d_in, const int* in_sizes, int n_in,
                              void* d_out, int out_size) {
    const float* x  = (const float*)d_in[0];
    const float* cx = (const float*)d_in[2];
    const int*   cy = (const int*)d_in[3];
    const float* W  = (const float*)d_in[4];
    const float* be = (const float*)d_in[5];
    float* out = (float*)d_out;

    int dev = 0;
    cudaGetDevice(&dev);
    int nsm = 148;
    cudaDeviceGetAttribute(&nsm, cudaDevAttrMultiProcessorCount, dev);
    if (nsm < 1 || nsm > MAX_CTAS) nsm = 148;

    cudaFuncSetAttribute(k_proj, cudaFuncAttributeMaxDynamicSharedMemorySize, SMEM_P2_BYTES);
    cudaFuncSetAttribute(k_main, cudaFuncAttributeMaxDynamicSharedMemorySize, SMEM_MAIN_BYTES);

    k_hist<<<NBLK, 256>>>(cy);
    k_scan<<<1, 320>>>();
    k_rank<<<NBLK, 256>>>(cy);
    k_proj<<<2 * nsm, 256, SMEM_P2_BYTES>>>(x, cx, W, be);
    k_main<<<nsm, 512, SMEM_MAIN_BYTES>>>();
    k_final<<<B_ROWS, 320>>>(out, nsm);
}